// round 4
// baseline (speedup 1.0000x reference)
#include <cuda_runtime.h>

#define XD 38
#define YD 24
#define ZD 24
#define RV (XD*YD*ZD)          // 21888
#define BB 16
#define CC 64
#define NN 16384
#define TOTVOX (BB*RV)         // 350208 (= 342*1024 = 5472*64)
#define NPTS   (BB*NN)         // 262144
#define SCAN_BLOCKS (TOTVOX/1024)   // 342
#define GATHER_BLOCKS (TOTVOX/64)   // 5472
#define GROUPS_PER_BATCH (RV/64)    // 342

// scratch (__device__ globals; zero-initialized at load; left clean every launch)
__device__ __align__(16) int   g_cnt [TOTVOX];
__device__ __align__(16) int   g_off [TOTVOX];
__device__ __align__(16) int   g_bsumIn[SCAN_BLOCKS];
__device__ __align__(16) int   g_bsum  [SCAN_BLOCKS];
__device__ __align__(16) int   g_flat[NPTS];
__device__ __align__(16) int   g_rank[NPTS];
__device__ __align__(16) float g_pfeat[(size_t)NPTS * CC];
__device__ int g_tick;

// ---------------- index ----------------
__global__ void index_k(const float4* __restrict__ coords4) {
    int t = blockIdx.x * blockDim.x + threadIdx.x;
    int p0 = t * 4;
    if (p0 >= NPTS) return;
    float4 a = coords4[t*3 + 0];
    float4 b = coords4[t*3 + 1];
    float4 c = coords4[t*3 + 2];
    float px[4] = {a.x, a.w, b.z, c.y};
    float py[4] = {a.y, b.x, b.w, c.z};
    float pz[4] = {a.z, b.y, c.x, c.w};
    int4 fl, rk;
    int* flp = &fl.x; int* rkp = &rk.x;
    int bidx = p0 / NN;
    #pragma unroll
    for (int k = 0; k < 4; k++) {
        int ix = (int)floorf(px[k] / 0.3f) + 19;
        int iy = (int)floorf(py[k] / 0.3f) + 12;
        int iz = (int)floorf(pz[k] / 0.2f) + 12;
        bool valid = (ix >= 0) & (ix < XD) & (iy >= 0) & (iy < YD) & (iz >= 0) & (iz < ZD);
        int flat = -1, rank = 0;
        if (valid) {
            flat = ix * (YD*ZD) + iy * ZD + iz;
            rank = atomicAdd(&g_cnt[bidx*RV + flat], 1);
        }
        flp[k] = flat; rkp[k] = rank;
    }
    *reinterpret_cast<int4*>(&g_flat[p0]) = fl;
    *reinterpret_cast<int4*>(&g_rank[p0]) = rk;
}

// ---------------- scan (fused two-level) ----------------
__global__ void scan_k() {
    __shared__ int wsum[8];
    int base = blockIdx.x * 1024 + threadIdx.x * 4;
    int4 v = *reinterpret_cast<const int4*>(&g_cnt[base]);
    int s = v.x + v.y + v.z + v.w;
    int lane = threadIdx.x & 31, wid = threadIdx.x >> 5;
    int sc = s;
    #pragma unroll
    for (int d = 1; d < 32; d <<= 1) {
        int n = __shfl_up_sync(0xFFFFFFFFu, sc, d);
        if (lane >= d) sc += n;
    }
    if (lane == 31) wsum[wid] = sc;
    __syncthreads();
    if (threadIdx.x == 0) {
        int run = 0;
        #pragma unroll
        for (int j = 0; j < 8; j++) { int tt = wsum[j]; wsum[j] = run; run += tt; }
        g_bsumIn[blockIdx.x] = run;
    }
    __syncthreads();
    int pre = (sc - s) + wsum[wid];
    int4 o; o.x = pre; o.y = pre + v.x; o.z = o.y + v.y; o.w = o.z + v.z;
    *reinterpret_cast<int4*>(&g_off[base]) = o;

    __shared__ bool amLast;
    __threadfence();
    if (threadIdx.x == 0) amLast = (atomicAdd(&g_tick, 1) == SCAN_BLOCKS - 1);
    __syncthreads();
    if (amLast && wid == 0) {
        __threadfence();
        int vals[11];
        #pragma unroll
        for (int j = 0; j < 11; j++) {
            int idx = j * 32 + lane;
            vals[j] = (idx < SCAN_BLOCKS) ? g_bsumIn[idx] : 0;
        }
        int run = 0;
        #pragma unroll
        for (int j = 0; j < 11; j++) {
            int x = vals[j], xs = x;
            #pragma unroll
            for (int d = 1; d < 32; d <<= 1) {
                int n = __shfl_up_sync(0xFFFFFFFFu, xs, d);
                if (lane >= d) xs += n;
            }
            int idx = j * 32 + lane;
            if (idx < SCAN_BLOCKS) g_bsum[idx] = run + xs - x;
            run += __shfl_sync(0xFFFFFFFFu, xs, 31);
        }
        if (lane == 0) g_tick = 0;
    }
}

// ---------------- permute ----------------
__global__ void permute_k(const float* __restrict__ feat) {
    __shared__ float sm[64][33];
    int b  = blockIdx.y;
    int p0 = blockIdx.x * 32;
    int t  = threadIdx.x;
    int j  = t & 31;
    int rb = t >> 5;
    const float* fb = feat + (size_t)b * CC * NN + p0 + j;
    #pragma unroll
    for (int k = 0; k < 8; k++) {
        int row = rb + k * 8;
        sm[row][j] = fb[(size_t)row * NN];
    }
    __syncthreads();
    int jp = t >> 3;
    int q  = t & 7;
    int i  = b * NN + p0 + jp;
    int flat = g_flat[i];
    if (flat >= 0) {
        int v = b * RV + flat;
        size_t slot = (size_t)(g_off[v] + g_bsum[v >> 10] + g_rank[i]);
        float* dst = g_pfeat + slot * CC + q * 8;
        int c0 = q * 8;
        float4 x = make_float4(sm[c0+0][jp], sm[c0+1][jp], sm[c0+2][jp], sm[c0+3][jp]);
        float4 y = make_float4(sm[c0+4][jp], sm[c0+5][jp], sm[c0+6][jp], sm[c0+7][jp]);
        *reinterpret_cast<float4*>(dst)     = x;
        *reinterpret_cast<float4*>(dst + 4) = y;
    }
}

// ---------------- gather: 256 thr, 8 warps x 8 voxels (two 4-voxel batches) ----------
__global__ __launch_bounds__(256, 6)
void gather_k(float* __restrict__ out) {
    __shared__ float sm[64 * 65];
    int t = threadIdx.x;
    int lane = t & 31, w = t >> 5;                // 8 warps
    int gvbase = blockIdx.x * 64;
    const float2* pf2 = reinterpret_cast<const float2*>(g_pfeat);

    #pragma unroll
    for (int half = 0; half < 2; half++) {
        int vox0 = w * 8 + half * 4;              // 0..60
        int gv = gvbase + vox0;
        int4 cnt4 = *reinterpret_cast<const int4*>(&g_cnt[gv]);
        int4 off4 = *reinterpret_cast<const int4*>(&g_off[gv]);
        int bs = g_bsum[gv >> 10];
        if (lane == 0) *reinterpret_cast<int4*>(&g_cnt[gv]) = make_int4(0,0,0,0);
        int cnt[4] = {cnt4.x, cnt4.y, cnt4.z, cnt4.w};
        int st [4] = {off4.x + bs, off4.y + bs, off4.z + bs, off4.w + bs};

        float ax[4] = {0.f,0.f,0.f,0.f}, ay[4] = {0.f,0.f,0.f,0.f};
        #pragma unroll
        for (int jj = 0; jj < 4; jj++) {
            #pragma unroll
            for (int lv = 0; lv < 4; lv++) {
                if (jj < cnt[lv]) {
                    float2 u = pf2[(size_t)(st[lv] + jj) * 32 + lane];
                    ax[lv] += u.x; ay[lv] += u.y;
                }
            }
        }
        int mx = max(max(cnt[0], cnt[1]), max(cnt[2], cnt[3]));
        if (mx > 4) {                             // rare (~0.3% of batches)
            #pragma unroll
            for (int lv = 0; lv < 4; lv++) {
                #pragma unroll 1
                for (int jj = 4; jj < cnt[lv]; jj++) {
                    float2 u = pf2[(size_t)(st[lv] + jj) * 32 + lane];
                    ax[lv] += u.x; ay[lv] += u.y;
                }
            }
        }
        #pragma unroll
        for (int lv = 0; lv < 4; lv++) {
            float inv = 1.f / (float)max(cnt[lv], 1);
            int vox = vox0 + lv;
            sm[(2*lane + 0) * 65 + vox] = ax[lv] * inv;
            sm[(2*lane + 1) * 65 + vox] = ay[lv] * inv;
        }
    }
    __syncthreads();

    int b  = blockIdx.x / GROUPS_PER_BATCH;
    int vb = (blockIdx.x % GROUPS_PER_BATCH) * 64;
    int c  = t >> 2;                              // 0..63
    int q  = t & 3;                               // 0..3 -> 16 voxels each
    float* ob = out + ((size_t)(b * CC + c)) * RV + vb + q * 16;
    const float* sp = &sm[c * 65 + q * 16];
    #pragma unroll
    for (int k = 0; k < 4; k++) {
        *reinterpret_cast<float4*>(ob + k*4) =
            make_float4(sp[k*4+0], sp[k*4+1], sp[k*4+2], sp[k*4+3]);
    }
}

extern "C" void kernel_launch(void* const* d_in, const int* in_sizes, int n_in,
                              void* d_out, int out_size) {
    const float* feat   = (const float*)d_in[0];   // [B, C, N]
    const float* coords = (const float*)d_in[1];   // [B, N, 3]
    float* out = (float*)d_out;                    // [B, C, X, Y, Z]

    index_k<<<NPTS / 4 / 256, 256>>>(reinterpret_cast<const float4*>(coords));
    scan_k<<<SCAN_BLOCKS, 256>>>();
    permute_k<<<dim3(NN / 32, BB), 256>>>(feat);
    gather_k<<<GATHER_BLOCKS, 256>>>(out);
}

// round 6
// speedup vs baseline: 1.7500x; 1.7500x over previous
#include <cuda_runtime.h>

#define XD 38
#define YD 24
#define ZD 24
#define RV (XD*YD*ZD)          // 21888
#define BB 16
#define CC 64
#define NN 16384
#define TOTVOX (BB*RV)         // 350208 (= 5472*64)
#define NPTS   (BB*NN)         // 262144
#define FIN_BLOCKS (TOTVOX/64)      // 5472
#define GROUPS_PER_BATCH (RV/64)    // 342

// scratch (__device__ globals; zero-initialized at load; self-cleaned every launch)
__device__ __align__(16) int   g_cnt[TOTVOX];                  // per-voxel count
__device__ __align__(16) int   g_flat[NPTS];                   // voxel id per point (-1 invalid)
__device__ __align__(16) float g_stage[(size_t)TOTVOX * CC];   // [B, R, C] accumulator (~90MB)

// vectorized global float reduction
__device__ __forceinline__ void red_add_v4(float* addr, float a, float b, float c, float d) {
    asm volatile("red.global.add.v4.f32 [%0], {%1, %2, %3, %4};"
                 :: "l"(addr), "f"(a), "f"(b), "f"(c), "f"(d) : "memory");
}

// ---------------- index: voxel id per point + counts (4 pts/thread) ----------------
__global__ void index_k(const float4* __restrict__ coords4) {
    int t = blockIdx.x * blockDim.x + threadIdx.x;
    int p0 = t * 4;
    if (p0 >= NPTS) return;
    float4 a = coords4[t*3 + 0];
    float4 b = coords4[t*3 + 1];
    float4 c = coords4[t*3 + 2];
    float px[4] = {a.x, a.w, b.z, c.y};
    float py[4] = {a.y, b.x, b.w, c.z};
    float pz[4] = {a.z, b.y, c.x, c.w};
    int4 fl;
    int* flp = &fl.x;
    int bidx = p0 / NN;                         // 4 pts never cross batch
    #pragma unroll
    for (int k = 0; k < 4; k++) {
        int ix = (int)floorf(px[k] / 0.3f) + 19;
        int iy = (int)floorf(py[k] / 0.3f) + 12;
        int iz = (int)floorf(pz[k] / 0.2f) + 12;
        bool valid = (ix >= 0) & (ix < XD) & (iy >= 0) & (iy < YD) & (iz >= 0) & (iz < ZD);
        int flat = -1;
        if (valid) {
            flat = ix * (YD*ZD) + iy * ZD + iz;
            atomicAdd(&g_cnt[bidx*RV + flat], 1);
        }
        flp[k] = flat;
    }
    *reinterpret_cast<int4*>(&g_flat[p0]) = fl;
}

// ---------------- scatter: feat [B,C,N] -> red.v4 into g_stage [B,R,C] ----------------
__global__ __launch_bounds__(256)
void scatter_k(const float* __restrict__ feat) {
    __shared__ float sm[64][33];
    int b  = blockIdx.y;
    int p0 = blockIdx.x * 32;
    int t  = threadIdx.x;
    int j  = t & 31;
    int rb = t >> 5;
    const float* fb = feat + (size_t)b * CC * NN + p0 + j;
    #pragma unroll
    for (int k = 0; k < 8; k++) {
        int row = rb + k * 8;
        sm[row][j] = fb[(size_t)row * NN];
    }
    __syncthreads();
    int jp = t >> 3;                  // point in tile 0..31
    int q  = t & 7;                   // channel octet 0..7
    int flat = g_flat[b * NN + p0 + jp];
    if (flat >= 0) {
        float* dst = g_stage + ((size_t)(b * RV + flat) * CC) + q * 8;
        int c0 = q * 8;
        red_add_v4(dst,     sm[c0+0][jp], sm[c0+1][jp], sm[c0+2][jp], sm[c0+3][jp]);
        red_add_v4(dst + 4, sm[c0+4][jp], sm[c0+5][jp], sm[c0+6][jp], sm[c0+7][jp]);
    }
}

// ---------------- finalize: staging -> averaged, transposed output; self-clean -------
__global__ __launch_bounds__(256)
void finalize_k(float* __restrict__ out) {
    __shared__ float sm[64 * 65];     // [channel][voxel]
    __shared__ float s_inv[64];
    __shared__ int   s_cnt[64];
    int t = threadIdx.x;
    int gvbase = blockIdx.x * 64;

    if (t < 64) {
        int c = g_cnt[gvbase + t];    // read, THEN clean (same thread -> ordered)
        s_cnt[t] = c;
        s_inv[t] = 1.f / (float)max(c, 1);
        g_cnt[gvbase + t] = 0;        // self-clean, race-free
    }
    __syncthreads();

    float4* stg4 = reinterpret_cast<float4*>(g_stage + (size_t)gvbase * CC);  // 1024 float4
    #pragma unroll
    for (int k = 0; k < 4; k++) {
        int i   = t + 256 * k;        // float4 index within block
        int vox = i >> 4;
        int c4  = i & 15;
        float4 v = stg4[i];
        float inv = s_inv[vox];
        int c0 = c4 * 4;
        sm[(c0+0) * 65 + vox] = v.x * inv;
        sm[(c0+1) * 65 + vox] = v.y * inv;
        sm[(c0+2) * 65 + vox] = v.z * inv;
        sm[(c0+3) * 65 + vox] = v.w * inv;
        if (s_cnt[vox] > 0) stg4[i] = make_float4(0.f, 0.f, 0.f, 0.f);  // self-clean
    }
    __syncthreads();

    int b  = blockIdx.x / GROUPS_PER_BATCH;
    int vb = (blockIdx.x % GROUPS_PER_BATCH) * 64;
    int c  = t >> 2;                  // 0..63
    int q  = t & 3;                   // 0..3 -> 16 voxels each
    float* ob = out + ((size_t)(b * CC + c)) * RV + vb + q * 16;
    const float* sp = &sm[c * 65 + q * 16];
    #pragma unroll
    for (int k = 0; k < 4; k++) {
        *reinterpret_cast<float4*>(ob + k*4) =
            make_float4(sp[k*4+0], sp[k*4+1], sp[k*4+2], sp[k*4+3]);
    }
}

extern "C" void kernel_launch(void* const* d_in, const int* in_sizes, int n_in,
                              void* d_out, int out_size) {
    const float* feat   = (const float*)d_in[0];   // [B, C, N]
    const float* coords = (const float*)d_in[1];   // [B, N, 3]
    float* out = (float*)d_out;                    // [B, C, X, Y, Z]

    index_k<<<NPTS / 4 / 256, 256>>>(reinterpret_cast<const float4*>(coords)); // 256 blocks
    scatter_k<<<dim3(NN / 32, BB), 256>>>(feat);                               // 8192 blocks
    finalize_k<<<FIN_BLOCKS, 256>>>(out);                                      // 5472 blocks
}